// round 2
// baseline (speedup 1.0000x reference)
#include <cuda_runtime.h>

#define B_    8
#define P_    96
#define D_    128
#define H_    256
#define NPTS  (B_*P_)          // 768
#define NPAIR (B_*P_*P_)       // 73728
#define K3    (3*H_)           // 768

// ---------------- device scratch (static allocs are allowed) ----------------
__device__ __align__(16) float g_Wcat[K3*H_];          // fused (W2@Wf) weights, [768,256]
__device__ __align__(16) float g_bias[H_];             // fused bias
__device__ __align__(16) float g_As[NPTS*H_];          // F@Ws1[0:D] + bs1
__device__ __align__(16) float g_Bs[NPTS*H_];          // F@Ws1[D:2D]
__device__ __align__(16) float g_At[NPTS*H_];          // F@Wt1[0:D] + bt1
__device__ __align__(16) float g_Bt[NPTS*H_];          // F@Wt1[D:2D]
__device__ __align__(16) float g_Ci[NPTS*H_];          // F@Wi1[D:2D]
__device__ __align__(16) float g_Hcat[(size_t)NPAIR*K3];  // relu'd hidden concat, 226.5 MB

// ---------------- kernel A: fuse layer-2 weights with final projection ------
__global__ void __launch_bounds__(256) prep_weights(
    const float* __restrict__ Ws2, const float* __restrict__ Wt2,
    const float* __restrict__ Wi2, const float* __restrict__ Wf,
    const float* __restrict__ bs2, const float* __restrict__ bt2,
    const float* __restrict__ bi2, const float* __restrict__ bff)
{
    int r = blockIdx.x;            // 0..767
    int h = threadIdx.x;           // 0..255
    int p = r >> 8;                // which branch
    int k = r & 255;
    const float* W2  = (p == 0) ? Ws2 : ((p == 1) ? Wt2 : Wi2);
    const float* Wfp = Wf + p * H_ * H_;
    float acc = 0.f;
    #pragma unroll 4
    for (int m = 0; m < H_; m++)
        acc = fmaf(W2[k*H_ + m], Wfp[m*H_ + h], acc);
    g_Wcat[r*H_ + h] = acc;

    if (r == 0) {
        float b = bff[h];
        for (int m = 0; m < H_; m++) {
            b = fmaf(bs2[m], Wf[m*H_ + h],          b);
            b = fmaf(bt2[m], Wf[(H_   + m)*H_ + h], b);
            b = fmaf(bi2[m], Wf[(2*H_ + m)*H_ + h], b);
        }
        g_bias[h] = b;
    }
}

// ---------------- kernel B: per-point projections (separable layer-1) -------
__global__ void __launch_bounds__(256) proj_points(
    const float* __restrict__ F,   const float* __restrict__ Ws1,
    const float* __restrict__ Wt1, const float* __restrict__ Wi1,
    const float* __restrict__ bs1, const float* __restrict__ bt1)
{
    __shared__ __align__(16) float sF[8][D_];
    int p0 = blockIdx.x * 8;       // 96 blocks of 8 points
    int h  = threadIdx.x;
    for (int t = h; t < 8*D_; t += 256) sF[t / D_][t % D_] = F[p0*D_ + t];
    __syncthreads();

    float as[8], bs[8], at[8], bt[8], ci[8];
    float b1 = bs1[h], b2 = bt1[h];
    #pragma unroll
    for (int r = 0; r < 8; r++) { as[r]=b1; bs[r]=0.f; at[r]=b2; bt[r]=0.f; ci[r]=0.f; }

    for (int d = 0; d < D_; d++) {
        float wsa = Ws1[d*H_ + h];
        float wsb = Ws1[(D_ + d)*H_ + h];
        float wta = Wt1[d*H_ + h];
        float wtb = Wt1[(D_ + d)*H_ + h];
        float wib = Wi1[(D_ + d)*H_ + h];
        #pragma unroll
        for (int r = 0; r < 8; r++) {
            float f = sF[r][d];
            as[r] = fmaf(f, wsa, as[r]);
            bs[r] = fmaf(f, wsb, bs[r]);
            at[r] = fmaf(f, wta, at[r]);
            bt[r] = fmaf(f, wtb, bt[r]);
            ci[r] = fmaf(f, wib, ci[r]);
        }
    }
    #pragma unroll
    for (int r = 0; r < 8; r++) {
        int idx = (p0 + r)*H_ + h;
        g_As[idx]=as[r]; g_Bs[idx]=bs[r]; g_At[idx]=at[r]; g_Bt[idx]=bt[r]; g_Ci[idx]=ci[r];
    }
}

// ---------------- kernel C: build relu'd hidden concat + bilinear -----------
__global__ void __launch_bounds__(256) build_hidden(
    const float* __restrict__ F,    const float* __restrict__ dist,
    const float* __restrict__ Wi1,  const float* __restrict__ Ws1,
    const float* __restrict__ bi1)
{
    __shared__ __align__(16) float sFi[D_];
    __shared__ __align__(16) float sDist[P_];
    __shared__ __align__(16) float sProd[8][D_];

    int bi = blockIdx.x;           // b*96 + i
    int b  = bi / P_;
    int h  = threadIdx.x;

    for (int t = h; t < D_; t += 256) sFi[t]   = F[bi*D_ + t];
    for (int t = h; t < P_; t += 256) sDist[t] = dist[bi*P_ + t];
    __syncthreads();

    float as_  = g_As[bi*H_ + h];
    float at_  = g_At[bi*H_ + h];
    float ci_i = g_Ci[bi*H_ + h];
    float w1c  = Ws1[2*D_*H_ + h];     // Ws1 row 256 (distance column)
    float bi1h = bi1[h];

    for (int jb = 0; jb < P_; jb += 8) {
        for (int t = h; t < 8*D_; t += 256) {
            int r = t / D_, d = t % D_;
            sProd[r][d] = sFi[d] * F[(b*P_ + jb + r)*D_ + d];
        }
        __syncthreads();

        float acc[8];
        #pragma unroll
        for (int r = 0; r < 8; r++) acc[r] = 0.f;

        for (int d = 0; d < D_; d += 4) {
            float w0 = Wi1[(d+0)*H_ + h];
            float w1 = Wi1[(d+1)*H_ + h];
            float w2 = Wi1[(d+2)*H_ + h];
            float w3 = Wi1[(d+3)*H_ + h];
            #pragma unroll
            for (int r = 0; r < 8; r++) {
                float4 pr = *(const float4*)&sProd[r][d];
                acc[r] = fmaf(pr.x, w0, acc[r]);
                acc[r] = fmaf(pr.y, w1, acc[r]);
                acc[r] = fmaf(pr.z, w2, acc[r]);
                acc[r] = fmaf(pr.w, w3, acc[r]);
            }
        }
        #pragma unroll
        for (int r = 0; r < 8; r++) {
            int j   = jb + r;
            int bj  = b*P_ + j;
            int row = bi*P_ + j;   // (b*96+i)*96 + j
            float hi = acc[r] + ci_i + g_Ci[bj*H_ + h] + bi1h;
            float hs = as_ + g_Bs[bj*H_ + h] + sDist[j]*w1c;
            float ht = at_ + g_Bt[bj*H_ + h];
            float* o = g_Hcat + (size_t)row * K3;
            o[h]        = fmaxf(hs, 0.f);
            o[H_ + h]   = fmaxf(ht, 0.f);
            o[2*H_ + h] = fmaxf(hi, 0.f);
        }
        __syncthreads();
    }
}

// ---------------- kernel D: out = Hcat @ Wcat + bias, * mask_pair -----------
#define BM 128
#define BN 128
#define BK 16
#define APAD 4   // row stride BM+4 = 132 floats = 528 B (16B-aligned), 4-bank shift/row

__global__ void __launch_bounds__(256) gemm_out_kernel(
    const float* __restrict__ mask, float* __restrict__ out)
{
    __shared__ __align__(16) float sA[BK][BM + APAD];   // transposed A tile
    __shared__ __align__(16) float sB[BK][BN];

    int m0 = blockIdx.x * BM;
    int n0 = blockIdx.y * BN;
    int tid  = threadIdx.x;
    int warp = tid >> 5, lane = tid & 31;
    int tm = (warp & 3) * 32 + (lane >> 3) * 8;   // thread row in tile
    int tn = (warp >> 2) * 64 + (lane & 7) * 8;   // thread col in tile

    float acc[8][8];
    #pragma unroll
    for (int x = 0; x < 8; x++)
        #pragma unroll
        for (int y = 0; y < 8; y++) acc[x][y] = 0.f;

    int la_row = tid >> 2;          // 0..63 (+64 second pass)
    int la_k   = (tid & 3) * 4;
    int lb_k   = tid >> 5;          // 0..7 (+8 second pass)
    int lb_n   = (tid & 31) * 4;

    for (int k0 = 0; k0 < K3; k0 += BK) {
        #pragma unroll
        for (int rr = 0; rr < 2; rr++) {
            int m = la_row + rr*64;
            float4 v = *(const float4*)&g_Hcat[(size_t)(m0 + m)*K3 + k0 + la_k];
            sA[la_k+0][m] = v.x; sA[la_k+1][m] = v.y;
            sA[la_k+2][m] = v.z; sA[la_k+3][m] = v.w;
        }
        #pragma unroll
        for (int rr = 0; rr < 2; rr++) {
            int k = lb_k + rr*8;
            *(float4*)&sB[k][lb_n] = *(const float4*)&g_Wcat[(k0 + k)*H_ + n0 + lb_n];
        }
        __syncthreads();

        #pragma unroll
        for (int k = 0; k < BK; k++) {
            float a[8], bb[8];
            *(float4*)&a[0]  = *(const float4*)&sA[k][tm];
            *(float4*)&a[4]  = *(const float4*)&sA[k][tm + 4];
            *(float4*)&bb[0] = *(const float4*)&sB[k][tn];
            *(float4*)&bb[4] = *(const float4*)&sB[k][tn + 4];
            #pragma unroll
            for (int x = 0; x < 8; x++)
                #pragma unroll
                for (int y = 0; y < 8; y++)
                    acc[x][y] = fmaf(a[x], bb[y], acc[x][y]);
        }
        __syncthreads();
    }

    float bias[8];
    #pragma unroll
    for (int y = 0; y < 8; y++) bias[y] = g_bias[n0 + tn + y];

    #pragma unroll
    for (int x = 0; x < 8; x++) {
        int row = m0 + tm + x;
        int b   = row / (P_*P_);
        int rem = row - b*(P_*P_);
        int i   = rem / P_;
        int j   = rem - i*P_;
        float mp = mask[b*P_ + i] * mask[b*P_ + j];
        float4 v0, v1;
        v0.x = (acc[x][0] + bias[0]) * mp;
        v0.y = (acc[x][1] + bias[1]) * mp;
        v0.z = (acc[x][2] + bias[2]) * mp;
        v0.w = (acc[x][3] + bias[3]) * mp;
        v1.x = (acc[x][4] + bias[4]) * mp;
        v1.y = (acc[x][5] + bias[5]) * mp;
        v1.z = (acc[x][6] + bias[6]) * mp;
        v1.w = (acc[x][7] + bias[7]) * mp;
        float* op = out + (size_t)row*H_ + n0 + tn;
        *(float4*)&op[0] = v0;
        *(float4*)&op[4] = v1;
    }
}

// ---------------- launch --------------------------------------------------
extern "C" void kernel_launch(void* const* d_in, const int* in_sizes, int n_in,
                              void* d_out, int out_size)
{
    const float* F    = (const float*)d_in[0];
    const float* dist = (const float*)d_in[1];
    const float* mask = (const float*)d_in[2];
    const float* Ws1  = (const float*)d_in[3];
    const float* bs1  = (const float*)d_in[4];
    const float* Ws2  = (const float*)d_in[5];
    const float* bs2  = (const float*)d_in[6];
    const float* Wt1  = (const float*)d_in[7];
    const float* bt1  = (const float*)d_in[8];
    const float* Wt2  = (const float*)d_in[9];
    const float* bt2  = (const float*)d_in[10];
    const float* Wi1  = (const float*)d_in[11];
    const float* bi1  = (const float*)d_in[12];
    const float* Wi2  = (const float*)d_in[13];
    const float* bi2  = (const float*)d_in[14];
    const float* Wf   = (const float*)d_in[15];
    const float* bff  = (const float*)d_in[16];
    float* out = (float*)d_out;

    prep_weights<<<K3, 256>>>(Ws2, Wt2, Wi2, Wf, bs2, bt2, bi2, bff);
    proj_points<<<NPTS/8, 256>>>(F, Ws1, Wt1, Wi1, bs1, bt1);
    build_hidden<<<NPTS, 256>>>(F, dist, Wi1, Ws1, bi1);
    dim3 grid(NPAIR / BM, H_ / BN);
    gemm_out_kernel<<<grid, 256>>>(mask, out);
}

// round 4
// speedup vs baseline: 1.5241x; 1.5241x over previous
#include <cuda_runtime.h>
#include <cstdint>

#define B_    8
#define P_    96
#define D_    128
#define H_    256
#define NPTS  (B_*P_)          // 768
#define NPAIR (B_*P_*P_)       // 73728
#define K3    (3*H_)           // 768

// ---------------- device scratch ----------------
__device__ __align__(16) float g_Wcat[K3*H_];
__device__ __align__(16) float g_bias[H_];
__device__ __align__(16) float g_As[NPTS*H_];
__device__ __align__(16) float g_Bs[NPTS*H_];
__device__ __align__(16) float g_At[NPTS*H_];
__device__ __align__(16) float g_Bt[NPTS*H_];
__device__ __align__(16) float g_Ci[NPTS*H_];
__device__ __align__(16) float g_Hcat[(size_t)NPAIR*K3];

__device__ __forceinline__ float f2tf32(float x) {
    uint32_t r;
    asm("cvt.rna.tf32.f32 %0, %1;" : "=r"(r) : "f"(x));
    return __uint_as_float(r);
}

// ---------------- kernel A: fuse layer-2 weights with final projection ------
__global__ void __launch_bounds__(256) prep_weights(
    const float* __restrict__ Ws2, const float* __restrict__ Wt2,
    const float* __restrict__ Wi2, const float* __restrict__ Wf,
    const float* __restrict__ bs2, const float* __restrict__ bt2,
    const float* __restrict__ bi2, const float* __restrict__ bff)
{
    int r = blockIdx.x;
    int h = threadIdx.x;
    int p = r >> 8;
    int k = r & 255;
    const float* W2  = (p == 0) ? Ws2 : ((p == 1) ? Wt2 : Wi2);
    const float* Wfp = Wf + p * H_ * H_;
    float acc = 0.f;
    #pragma unroll 4
    for (int m = 0; m < H_; m++)
        acc = fmaf(W2[k*H_ + m], Wfp[m*H_ + h], acc);
    g_Wcat[r*H_ + h] = acc;

    if (r == 0) {
        float b = bff[h];
        for (int m = 0; m < H_; m++) {
            b = fmaf(bs2[m], Wf[m*H_ + h],          b);
            b = fmaf(bt2[m], Wf[(H_   + m)*H_ + h], b);
            b = fmaf(bi2[m], Wf[(2*H_ + m)*H_ + h], b);
        }
        g_bias[h] = b;
    }
}

// ---------------- kernel B: per-point projections ----------------
__global__ void __launch_bounds__(256) proj_points(
    const float* __restrict__ F,   const float* __restrict__ Ws1,
    const float* __restrict__ Wt1, const float* __restrict__ Wi1,
    const float* __restrict__ bs1, const float* __restrict__ bt1)
{
    __shared__ __align__(16) float sF[8][D_];
    int p0 = blockIdx.x * 8;
    int h  = threadIdx.x;
    for (int t = h; t < 8*D_; t += 256) sF[t / D_][t % D_] = F[p0*D_ + t];
    __syncthreads();

    float as[8], bs[8], at[8], bt[8], ci[8];
    float b1 = bs1[h], b2 = bt1[h];
    #pragma unroll
    for (int r = 0; r < 8; r++) { as[r]=b1; bs[r]=0.f; at[r]=b2; bt[r]=0.f; ci[r]=0.f; }

    for (int d = 0; d < D_; d++) {
        float wsa = Ws1[d*H_ + h];
        float wsb = Ws1[(D_ + d)*H_ + h];
        float wta = Wt1[d*H_ + h];
        float wtb = Wt1[(D_ + d)*H_ + h];
        float wib = Wi1[(D_ + d)*H_ + h];
        #pragma unroll
        for (int r = 0; r < 8; r++) {
            float f = sF[r][d];
            as[r] = fmaf(f, wsa, as[r]);
            bs[r] = fmaf(f, wsb, bs[r]);
            at[r] = fmaf(f, wta, at[r]);
            bt[r] = fmaf(f, wtb, bt[r]);
            ci[r] = fmaf(f, wib, ci[r]);
        }
    }
    #pragma unroll
    for (int r = 0; r < 8; r++) {
        int idx = (p0 + r)*H_ + h;
        g_As[idx]=as[r]; g_Bs[idx]=bs[r]; g_At[idx]=at[r]; g_Bt[idx]=bt[r]; g_Ci[idx]=ci[r];
    }
}

// ---------------- kernel C: build relu'd hidden concat + bilinear -----------
__global__ void __launch_bounds__(256) build_hidden(
    const float* __restrict__ F,    const float* __restrict__ dist,
    const float* __restrict__ Wi1,  const float* __restrict__ Ws1,
    const float* __restrict__ bi1)
{
    __shared__ __align__(16) float sFi[D_];
    __shared__ __align__(16) float sDist[P_];
    __shared__ __align__(16) float sProd[8][D_];

    int bi = blockIdx.x;
    int b  = bi / P_;
    int h  = threadIdx.x;

    for (int t = h; t < D_; t += 256) sFi[t]   = F[bi*D_ + t];
    for (int t = h; t < P_; t += 256) sDist[t] = dist[bi*P_ + t];
    __syncthreads();

    float as_  = g_As[bi*H_ + h];
    float at_  = g_At[bi*H_ + h];
    float ci_i = g_Ci[bi*H_ + h];
    float w1c  = Ws1[2*D_*H_ + h];
    float bi1h = bi1[h];

    for (int jb = 0; jb < P_; jb += 8) {
        for (int t = h; t < 8*D_; t += 256) {
            int r = t / D_, d = t % D_;
            sProd[r][d] = sFi[d] * F[(b*P_ + jb + r)*D_ + d];
        }
        __syncthreads();

        float acc[8];
        #pragma unroll
        for (int r = 0; r < 8; r++) acc[r] = 0.f;

        for (int d = 0; d < D_; d += 4) {
            float w0 = Wi1[(d+0)*H_ + h];
            float w1 = Wi1[(d+1)*H_ + h];
            float w2 = Wi1[(d+2)*H_ + h];
            float w3 = Wi1[(d+3)*H_ + h];
            #pragma unroll
            for (int r = 0; r < 8; r++) {
                float4 pr = *(const float4*)&sProd[r][d];
                acc[r] = fmaf(pr.x, w0, acc[r]);
                acc[r] = fmaf(pr.y, w1, acc[r]);
                acc[r] = fmaf(pr.z, w2, acc[r]);
                acc[r] = fmaf(pr.w, w3, acc[r]);
            }
        }
        #pragma unroll
        for (int r = 0; r < 8; r++) {
            int j   = jb + r;
            int bj  = b*P_ + j;
            int row = bi*P_ + j;
            float hi = acc[r] + ci_i + g_Ci[bj*H_ + h] + bi1h;
            float hs = as_ + g_Bs[bj*H_ + h] + sDist[j]*w1c;
            float ht = at_ + g_Bt[bj*H_ + h];
            float* o = g_Hcat + (size_t)row * K3;
            o[h]        = fmaxf(hs, 0.f);
            o[H_ + h]   = fmaxf(ht, 0.f);
            o[2*H_ + h] = fmaxf(hi, 0.f);
        }
        __syncthreads();
    }
}

// ---------------- kernel D: tf32 tensor-core GEMM + fused epilogue ----------
// out = Hcat @ Wcat + bias, * mask_pair.  M=73728, N=256, K=768.
#define BM  128
#define BN  128
#define BKT 16
#define PAD 4

__global__ void __launch_bounds__(256) gemm_out_tc(
    const float* __restrict__ mask, float* __restrict__ out)
{
    __shared__ __align__(16) float sA[BKT][BM + PAD];
    __shared__ __align__(16) float sB[BKT][BN + PAD];

    int m0 = blockIdx.x * BM;
    int n0 = blockIdx.y * BN;
    int tid  = threadIdx.x;
    int warp = tid >> 5, lane = tid & 31;
    int wm   = warp >> 1;        // 0..3 -> 32 rows
    int wn   = warp & 1;         // 0..1 -> 64 cols
    int grp  = lane >> 2;        // 0..7
    int thr  = lane & 3;         // 0..3

    float acc[2][8][4];
    #pragma unroll
    for (int mt = 0; mt < 2; mt++)
        #pragma unroll
        for (int nt = 0; nt < 8; nt++)
            #pragma unroll
            for (int c = 0; c < 4; c++) acc[mt][nt][c] = 0.f;

    // global-load assignments
    int la_row = tid >> 2;            // 0..63 (+64)
    int la_k   = (tid & 3) * 4;       // 0,4,8,12
    int lb_k   = tid >> 5;            // 0..7 (+8)
    int lb_n   = (tid & 31) * 4;      // 0..124

    float4 ra[2], rb[2];
    const float* Ap = g_Hcat + (size_t)(m0 + la_row) * K3 + la_k;
    const float* Bp = g_Wcat + (size_t)lb_k * H_ + n0 + lb_n;

    // prologue load k0 = 0
    ra[0] = *(const float4*)(Ap);
    ra[1] = *(const float4*)(Ap + (size_t)64 * K3);
    rb[0] = *(const float4*)(Bp);
    rb[1] = *(const float4*)(Bp + 8 * H_);

    for (int k0 = 0; k0 < K3; k0 += BKT) {
        // store current tile to smem with tf32 rounding
        sA[la_k+0][la_row]      = f2tf32(ra[0].x);
        sA[la_k+1][la_row]      = f2tf32(ra[0].y);
        sA[la_k+2][la_row]      = f2tf32(ra[0].z);
        sA[la_k+3][la_row]      = f2tf32(ra[0].w);
        sA[la_k+0][la_row + 64] = f2tf32(ra[1].x);
        sA[la_k+1][la_row + 64] = f2tf32(ra[1].y);
        sA[la_k+2][la_row + 64] = f2tf32(ra[1].z);
        sA[la_k+3][la_row + 64] = f2tf32(ra[1].w);
        float4 b0 = rb[0], b1 = rb[1];
        b0.x = f2tf32(b0.x); b0.y = f2tf32(b0.y); b0.z = f2tf32(b0.z); b0.w = f2tf32(b0.w);
        b1.x = f2tf32(b1.x); b1.y = f2tf32(b1.y); b1.z = f2tf32(b1.z); b1.w = f2tf32(b1.w);
        *(float4*)&sB[lb_k][lb_n]     = b0;
        *(float4*)&sB[lb_k + 8][lb_n] = b1;
        __syncthreads();

        // prefetch next tile into registers (latency hidden by mma)
        if (k0 + BKT < K3) {
            ra[0] = *(const float4*)(Ap + k0 + BKT);
            ra[1] = *(const float4*)(Ap + (size_t)64 * K3 + k0 + BKT);
            rb[0] = *(const float4*)(Bp + (size_t)(k0 + BKT) * H_);
            rb[1] = *(const float4*)(Bp + (size_t)(k0 + BKT + 8) * H_);
        }

        #pragma unroll
        for (int ks = 0; ks < 2; ks++) {
            int kb = ks * 8;
            uint32_t af[2][4], bf[8][2];
            #pragma unroll
            for (int mt = 0; mt < 2; mt++) {
                int row = wm * 32 + mt * 16 + grp;
                af[mt][0] = __float_as_uint(sA[kb + thr    ][row]);
                af[mt][1] = __float_as_uint(sA[kb + thr    ][row + 8]);
                af[mt][2] = __float_as_uint(sA[kb + thr + 4][row]);
                af[mt][3] = __float_as_uint(sA[kb + thr + 4][row + 8]);
            }
            #pragma unroll
            for (int nt = 0; nt < 8; nt++) {
                int col = wn * 64 + nt * 8 + grp;
                bf[nt][0] = __float_as_uint(sB[kb + thr    ][col]);
                bf[nt][1] = __float_as_uint(sB[kb + thr + 4][col]);
            }
            #pragma unroll
            for (int mt = 0; mt < 2; mt++)
                #pragma unroll
                for (int nt = 0; nt < 8; nt++) {
                    asm volatile(
                        "mma.sync.aligned.m16n8k8.row.col.f32.tf32.tf32.f32 "
                        "{%0,%1,%2,%3}, {%4,%5,%6,%7}, {%8,%9}, {%0,%1,%2,%3};"
                        : "+f"(acc[mt][nt][0]), "+f"(acc[mt][nt][1]),
                          "+f"(acc[mt][nt][2]), "+f"(acc[mt][nt][3])
                        : "r"(af[mt][0]), "r"(af[mt][1]), "r"(af[mt][2]), "r"(af[mt][3]),
                          "r"(bf[nt][0]), "r"(bf[nt][1]));
                }
        }
        __syncthreads();
    }

    // ---------------- epilogue: bias + mask, write ----------------
    #pragma unroll
    for (int mt = 0; mt < 2; mt++) {
        int r0 = m0 + wm * 32 + mt * 16 + grp;   // and r0+8
        #pragma unroll
        for (int half = 0; half < 2; half++) {
            int row = r0 + half * 8;
            int b   = row / (P_*P_);
            int rem = row - b * (P_*P_);
            int i   = rem / P_;
            int j   = rem - i * P_;
            float mp = mask[b*P_ + i] * mask[b*P_ + j];
            #pragma unroll
            for (int nt = 0; nt < 8; nt++) {
                int col = n0 + wn * 64 + nt * 8 + thr * 2;
                float2 v;
                v.x = (acc[mt][nt][half*2 + 0] + g_bias[col])     * mp;
                v.y = (acc[mt][nt][half*2 + 1] + g_bias[col + 1]) * mp;
                *(float2*)&out[(size_t)row * H_ + col] = v;
            }
        }
    }
}

// ---------------- launch --------------------------------------------------
extern "C" void kernel_launch(void* const* d_in, const int* in_sizes, int n_in,
                              void* d_out, int out_size)
{
    const float* F    = (const float*)d_in[0];
    const float* dist = (const float*)d_in[1];
    const float* mask = (const float*)d_in[2];
    const float* Ws1  = (const float*)d_in[3];
    const float* bs1  = (const float*)d_in[4];
    const float* Ws2  = (const float*)d_in[5];
    const float* bs2  = (const float*)d_in[6];
    const float* Wt1  = (const float*)d_in[7];
    const float* bt1  = (const float*)d_in[8];
    const float* Wt2  = (const float*)d_in[9];
    const float* bt2  = (const float*)d_in[10];
    const float* Wi1  = (const float*)d_in[11];
    const float* bi1  = (const float*)d_in[12];
    const float* Wi2  = (const float*)d_in[13];
    const float* bi2  = (const float*)d_in[14];
    const float* Wf   = (const float*)d_in[15];
    const float* bff  = (const float*)d_in[16];
    float* out = (float*)d_out;

    prep_weights<<<K3, 256>>>(Ws2, Wt2, Wi2, Wf, bs2, bt2, bi2, bff);
    proj_points<<<NPTS/8, 256>>>(F, Ws1, Wt1, Wi1, bs1, bt1);
    build_hidden<<<NPTS, 256>>>(F, dist, Wi1, Ws1, bi1);
    dim3 grid(NPAIR / BM, H_ / BN);
    gemm_out_tc<<<grid, 256>>>(mask, out);
}

// round 5
// speedup vs baseline: 1.8466x; 1.2116x over previous
#include <cuda_runtime.h>
#include <cstdint>

#define B_    8
#define P_    96
#define D_    128
#define H_    256
#define NPTS  (B_*P_)          // 768
#define NPAIR (B_*P_*P_)       // 73728
#define K3    (3*H_)           // 768

// ---------------- device scratch ----------------
__device__ __align__(16) float g_Wcat[K3*H_];          // fused (W2@Wf), tf32-rounded
__device__ __align__(16) float g_bias[H_];
__device__ __align__(16) float g_As[NPTS*H_];
__device__ __align__(16) float g_Bs[NPTS*H_];
__device__ __align__(16) float g_At[NPTS*H_];
__device__ __align__(16) float g_Bt[NPTS*H_];
__device__ __align__(16) float g_Ci[NPTS*H_];
__device__ __align__(16) float g_Hi[(size_t)NPAIR*H_]; // relu'd interaction hidden, tf32-rounded, 75.5MB

__device__ __forceinline__ float f2tf32(float x) {
    uint32_t r;
    asm("cvt.rna.tf32.f32 %0, %1;" : "=r"(r) : "f"(x));
    return __uint_as_float(r);
}

// ---------------- kernel A: fuse layer-2 weights with final projection ------
__global__ void __launch_bounds__(256) prep_weights(
    const float* __restrict__ Ws2, const float* __restrict__ Wt2,
    const float* __restrict__ Wi2, const float* __restrict__ Wf,
    const float* __restrict__ bs2, const float* __restrict__ bt2,
    const float* __restrict__ bi2, const float* __restrict__ bff)
{
    int r = blockIdx.x;
    int h = threadIdx.x;
    int p = r >> 8;
    int k = r & 255;
    const float* W2  = (p == 0) ? Ws2 : ((p == 1) ? Wt2 : Wi2);
    const float* Wfp = Wf + p * H_ * H_;
    float acc = 0.f;
    #pragma unroll 4
    for (int m = 0; m < H_; m++)
        acc = fmaf(W2[k*H_ + m], Wfp[m*H_ + h], acc);
    g_Wcat[r*H_ + h] = f2tf32(acc);     // pre-round: GEMM loads raw

    if (r == 0) {
        float b = bff[h];
        for (int m = 0; m < H_; m++) {
            b = fmaf(bs2[m], Wf[m*H_ + h],          b);
            b = fmaf(bt2[m], Wf[(H_   + m)*H_ + h], b);
            b = fmaf(bi2[m], Wf[(2*H_ + m)*H_ + h], b);
        }
        g_bias[h] = b;
    }
}

// ---------------- kernel B: per-point projections ----------------
__global__ void __launch_bounds__(256) proj_points(
    const float* __restrict__ F,   const float* __restrict__ Ws1,
    const float* __restrict__ Wt1, const float* __restrict__ Wi1,
    const float* __restrict__ bs1, const float* __restrict__ bt1)
{
    __shared__ __align__(16) float sF[8][D_];
    int p0 = blockIdx.x * 8;
    int h  = threadIdx.x;
    for (int t = h; t < 8*D_; t += 256) sF[t / D_][t % D_] = F[p0*D_ + t];
    __syncthreads();

    float as[8], bs[8], at[8], bt[8], ci[8];
    float b1 = bs1[h], b2 = bt1[h];
    #pragma unroll
    for (int r = 0; r < 8; r++) { as[r]=b1; bs[r]=0.f; at[r]=b2; bt[r]=0.f; ci[r]=0.f; }

    for (int d = 0; d < D_; d++) {
        float wsa = Ws1[d*H_ + h];
        float wsb = Ws1[(D_ + d)*H_ + h];
        float wta = Wt1[d*H_ + h];
        float wtb = Wt1[(D_ + d)*H_ + h];
        float wib = Wi1[(D_ + d)*H_ + h];
        #pragma unroll
        for (int r = 0; r < 8; r++) {
            float f = sF[r][d];
            as[r] = fmaf(f, wsa, as[r]);
            bs[r] = fmaf(f, wsb, bs[r]);
            at[r] = fmaf(f, wta, at[r]);
            bt[r] = fmaf(f, wtb, bt[r]);
            ci[r] = fmaf(f, wib, ci[r]);
        }
    }
    #pragma unroll
    for (int r = 0; r < 8; r++) {
        int idx = (p0 + r)*H_ + h;
        g_As[idx]=as[r]; g_Bs[idx]=bs[r]; g_At[idx]=at[r]; g_Bt[idx]=bt[r]; g_Ci[idx]=ci[r];
    }
}

// ---------------- kernel C: interaction hidden via tf32 tensor cores --------
// CTA = (b,i). Hi[j,h] = relu( (f_i .* f_j) @ Wi1a + Ci[i,h] + Ci[j,h] + bi1[h] )
// M=96, N=256, K=128.  384 threads, 12 warps = 3(m) x 4(n), warp tile 32x64.
__global__ void __launch_bounds__(384) bilinear_hi(
    const float* __restrict__ F, const float* __restrict__ Wi1,
    const float* __restrict__ bi1)
{
    __shared__ __align__(16) float sP[16][96 + 8];     // stride 104 (8 mod 32)
    __shared__ __align__(16) float sW[16][256 + 8];    // stride 264 (8 mod 32)
    __shared__ float sFi[D_], sCii[H_], sBi1[H_];

    int bi = blockIdx.x;
    int b  = bi / P_;
    int tid  = threadIdx.x;
    int warp = tid >> 5, lane = tid & 31;
    int wm = warp >> 2, wn = warp & 3;      // 3 x 4
    int grp = lane >> 2, thr = lane & 3;

    for (int t = tid; t < D_; t += 384) sFi[t] = F[bi*D_ + t];
    for (int t = tid; t < H_; t += 384) { sCii[t] = g_Ci[bi*H_ + t]; sBi1[t] = bi1[t]; }
    __syncthreads();

    int j_a = tid >> 2, k_a = (tid & 3) << 2;
    const float* rowF = F + (b*P_ + j_a) * D_;

    float acc[2][8][4];
    #pragma unroll
    for (int mt = 0; mt < 2; mt++)
        #pragma unroll
        for (int nt = 0; nt < 8; nt++)
            #pragma unroll
            for (int c = 0; c < 4; c++) acc[mt][nt][c] = 0.f;

    for (int d0 = 0; d0 < D_; d0 += 16) {
        if (d0) __syncthreads();
        // build P tile: sP[k][j] = tf32(f_i[d] * f_j[d])
        float4 v = *(const float4*)(rowF + d0 + k_a);
        sP[k_a+0][j_a] = f2tf32(sFi[d0+k_a+0] * v.x);
        sP[k_a+1][j_a] = f2tf32(sFi[d0+k_a+1] * v.y);
        sP[k_a+2][j_a] = f2tf32(sFi[d0+k_a+2] * v.z);
        sP[k_a+3][j_a] = f2tf32(sFi[d0+k_a+3] * v.w);
        // load Wi1a tile (rows d0..d0+16, all 256 cols)
        for (int idx = tid; idx < 16*64; idx += 384) {
            int k = idx >> 6, n4 = (idx & 63) << 2;
            float4 w = *(const float4*)(&Wi1[(d0 + k)*H_ + n4]);
            w.x = f2tf32(w.x); w.y = f2tf32(w.y); w.z = f2tf32(w.z); w.w = f2tf32(w.w);
            *(float4*)&sW[k][n4] = w;
        }
        __syncthreads();

        #pragma unroll
        for (int ks = 0; ks < 2; ks++) {
            int kb = ks * 8;
            uint32_t af[2][4], bf[8][2];
            #pragma unroll
            for (int mt = 0; mt < 2; mt++) {
                int row = wm*32 + mt*16 + grp;
                af[mt][0] = __float_as_uint(sP[kb + thr    ][row]);
                af[mt][1] = __float_as_uint(sP[kb + thr    ][row + 8]);
                af[mt][2] = __float_as_uint(sP[kb + thr + 4][row]);
                af[mt][3] = __float_as_uint(sP[kb + thr + 4][row + 8]);
            }
            #pragma unroll
            for (int nt = 0; nt < 8; nt++) {
                int col = wn*64 + nt*8 + grp;
                bf[nt][0] = __float_as_uint(sW[kb + thr    ][col]);
                bf[nt][1] = __float_as_uint(sW[kb + thr + 4][col]);
            }
            #pragma unroll
            for (int mt = 0; mt < 2; mt++)
                #pragma unroll
                for (int nt = 0; nt < 8; nt++)
                    asm volatile(
                        "mma.sync.aligned.m16n8k8.row.col.f32.tf32.tf32.f32 "
                        "{%0,%1,%2,%3}, {%4,%5,%6,%7}, {%8,%9}, {%0,%1,%2,%3};"
                        : "+f"(acc[mt][nt][0]), "+f"(acc[mt][nt][1]),
                          "+f"(acc[mt][nt][2]), "+f"(acc[mt][nt][3])
                        : "r"(af[mt][0]), "r"(af[mt][1]), "r"(af[mt][2]), "r"(af[mt][3]),
                          "r"(bf[nt][0]), "r"(bf[nt][1]));
        }
    }

    // epilogue: + Ci_i + Ci_j + bi1, relu, tf32-round, store
    #pragma unroll
    for (int mt = 0; mt < 2; mt++) {
        #pragma unroll
        for (int half = 0; half < 2; half++) {
            int j = wm*32 + mt*16 + grp + half*8;
            const float* cij = g_Ci + (b*P_ + j)*H_;
            size_t obase = ((size_t)bi*P_ + j)*H_;
            #pragma unroll
            for (int nt = 0; nt < 8; nt++) {
                int col = wn*64 + nt*8 + thr*2;
                float2 v;
                v.x = f2tf32(fmaxf(acc[mt][nt][half*2+0] + sCii[col]   + cij[col]   + sBi1[col],   0.f));
                v.y = f2tf32(fmaxf(acc[mt][nt][half*2+1] + sCii[col+1] + cij[col+1] + sBi1[col+1], 0.f));
                *(float2*)&g_Hi[obase + col] = v;
            }
        }
    }
}

// ---------------- kernel D: fused GEMM with on-the-fly A tiles --------------
// CTA = (b,i) x n-half. out[j,n] = sum_k relu(H[j,k]) * Wcat[k,n] + bias, * mask.
// M=96, N=128, K=768. 384 threads, 12 warps = 3(m) x 4(n), warp tile 32x32.
#define DN 128

__global__ void __launch_bounds__(384) gemm_fused(
    const float* __restrict__ dist, const float* __restrict__ mask,
    const float* __restrict__ Ws1,  float* __restrict__ out)
{
    __shared__ __align__(16) float sA[16][96 + 8];     // stride 104
    __shared__ __align__(16) float sB[16][DN + 8];     // stride 136
    __shared__ float sAsi[H_], sAti[H_], sW1c[H_];

    int bi = blockIdx.x;
    int b  = bi / P_;
    int n0 = blockIdx.y * DN;
    int tid  = threadIdx.x;
    int warp = tid >> 5, lane = tid & 31;
    int wm = warp >> 2, wn = warp & 3;      // 3 x 4
    int grp = lane >> 2, thr = lane & 3;

    for (int t = tid; t < H_; t += 384) {
        sAsi[t] = g_As[bi*H_ + t];
        sAti[t] = g_At[bi*H_ + t];
        sW1c[t] = Ws1[2*D_*H_ + t];        // Ws1 row 256 (distance)
    }
    __syncthreads();

    int j_a = tid >> 2, k_a = (tid & 3) << 2;
    const float* rowBs = g_Bs + (b*P_ + j_a)*H_;
    const float* rowBt = g_Bt + (b*P_ + j_a)*H_;
    const float* rowHi = g_Hi + ((size_t)bi*P_ + j_a)*H_;
    float dj = dist[bi*P_ + j_a];

    // sB loaders: 16 x 128 floats = 512 float4; idx = tid (k=idx>>5, n4=(idx&31)*4), +384 for tid<128
    int sb_k0 = tid >> 5,          sb_n0 = (tid & 31) << 2;
    int sb_k1 = (tid + 384) >> 5,  sb_n1 = ((tid + 384) & 31) << 2;

    float acc[2][4][4];
    #pragma unroll
    for (int mt = 0; mt < 2; mt++)
        #pragma unroll
        for (int nt = 0; nt < 4; nt++)
            #pragma unroll
            for (int c = 0; c < 4; c++) acc[mt][nt][c] = 0.f;

    // prologue prefetch (k0 = 0, phase S)
    float4 va  = *(const float4*)(rowBs + k_a);
    float4 vb0 = *(const float4*)(&g_Wcat[sb_k0*H_ + n0 + sb_n0]);
    float4 vb1;
    if (tid < 128) vb1 = *(const float4*)(&g_Wcat[sb_k1*H_ + n0 + sb_n1]);

    for (int k0 = 0; k0 < K3; k0 += 16) {
        // build A tile
        float4 a;
        if (k0 < 256) {
            int kk = k0 + k_a;
            a.x = f2tf32(fmaxf(sAsi[kk+0] + va.x + dj*sW1c[kk+0], 0.f));
            a.y = f2tf32(fmaxf(sAsi[kk+1] + va.y + dj*sW1c[kk+1], 0.f));
            a.z = f2tf32(fmaxf(sAsi[kk+2] + va.z + dj*sW1c[kk+2], 0.f));
            a.w = f2tf32(fmaxf(sAsi[kk+3] + va.w + dj*sW1c[kk+3], 0.f));
        } else if (k0 < 512) {
            int kk = k0 - 256 + k_a;
            a.x = f2tf32(fmaxf(sAti[kk+0] + va.x, 0.f));
            a.y = f2tf32(fmaxf(sAti[kk+1] + va.y, 0.f));
            a.z = f2tf32(fmaxf(sAti[kk+2] + va.z, 0.f));
            a.w = f2tf32(fmaxf(sAti[kk+3] + va.w, 0.f));
        } else {
            a = va;   // g_Hi already relu'd + tf32-rounded
        }
        sA[k_a+0][j_a] = a.x; sA[k_a+1][j_a] = a.y;
        sA[k_a+2][j_a] = a.z; sA[k_a+3][j_a] = a.w;
        *(float4*)&sB[sb_k0][sb_n0] = vb0;
        if (tid < 128) *(float4*)&sB[sb_k1][sb_n1] = vb1;
        __syncthreads();

        // prefetch next stage while mma runs
        int kn = k0 + 16;
        if (kn < K3) {
            const float* src = (kn < 256) ? (rowBs + kn)
                             : (kn < 512) ? (rowBt + (kn - 256))
                                          : (rowHi + (kn - 512));
            va  = *(const float4*)(src + k_a);
            vb0 = *(const float4*)(&g_Wcat[(kn + sb_k0)*H_ + n0 + sb_n0]);
            if (tid < 128) vb1 = *(const float4*)(&g_Wcat[(kn + sb_k1)*H_ + n0 + sb_n1]);
        }

        #pragma unroll
        for (int ks = 0; ks < 2; ks++) {
            int kb = ks * 8;
            uint32_t af[2][4], bf[4][2];
            #pragma unroll
            for (int mt = 0; mt < 2; mt++) {
                int row = wm*32 + mt*16 + grp;
                af[mt][0] = __float_as_uint(sA[kb + thr    ][row]);
                af[mt][1] = __float_as_uint(sA[kb + thr    ][row + 8]);
                af[mt][2] = __float_as_uint(sA[kb + thr + 4][row]);
                af[mt][3] = __float_as_uint(sA[kb + thr + 4][row + 8]);
            }
            #pragma unroll
            for (int nt = 0; nt < 4; nt++) {
                int col = wn*32 + nt*8 + grp;
                bf[nt][0] = __float_as_uint(sB[kb + thr    ][col]);
                bf[nt][1] = __float_as_uint(sB[kb + thr + 4][col]);
            }
            #pragma unroll
            for (int mt = 0; mt < 2; mt++)
                #pragma unroll
                for (int nt = 0; nt < 4; nt++)
                    asm volatile(
                        "mma.sync.aligned.m16n8k8.row.col.f32.tf32.tf32.f32 "
                        "{%0,%1,%2,%3}, {%4,%5,%6,%7}, {%8,%9}, {%0,%1,%2,%3};"
                        : "+f"(acc[mt][nt][0]), "+f"(acc[mt][nt][1]),
                          "+f"(acc[mt][nt][2]), "+f"(acc[mt][nt][3])
                        : "r"(af[mt][0]), "r"(af[mt][1]), "r"(af[mt][2]), "r"(af[mt][3]),
                          "r"(bf[nt][0]), "r"(bf[nt][1]));
        }
        __syncthreads();
    }

    // epilogue
    float mi = mask[bi];
    #pragma unroll
    for (int mt = 0; mt < 2; mt++) {
        #pragma unroll
        for (int half = 0; half < 2; half++) {
            int j = wm*32 + mt*16 + grp + half*8;
            float mp = mi * mask[b*P_ + j];
            size_t obase = ((size_t)bi*P_ + j)*H_ + n0;
            #pragma unroll
            for (int nt = 0; nt < 4; nt++) {
                int col = wn*32 + nt*8 + thr*2;
                float2 v;
                v.x = (acc[mt][nt][half*2+0] + g_bias[n0 + col])     * mp;
                v.y = (acc[mt][nt][half*2+1] + g_bias[n0 + col + 1]) * mp;
                *(float2*)&out[obase + col] = v;
            }
        }
    }
}

// ---------------- launch --------------------------------------------------
extern "C" void kernel_launch(void* const* d_in, const int* in_sizes, int n_in,
                              void* d_out, int out_size)
{
    const float* F    = (const float*)d_in[0];
    const float* dist = (const float*)d_in[1];
    const float* mask = (const float*)d_in[2];
    const float* Ws1  = (const float*)d_in[3];
    const float* bs1  = (const float*)d_in[4];
    const float* Ws2  = (const float*)d_in[5];
    const float* bs2  = (const float*)d_in[6];
    const float* Wt1  = (const float*)d_in[7];
    const float* bt1  = (const float*)d_in[8];
    const float* Wt2  = (const float*)d_in[9];
    const float* bt2  = (const float*)d_in[10];
    const float* Wi1  = (const float*)d_in[11];
    const float* bi1  = (const float*)d_in[12];
    const float* Wi2  = (const float*)d_in[13];
    const float* bi2  = (const float*)d_in[14];
    const float* Wf   = (const float*)d_in[15];
    const float* bff  = (const float*)d_in[16];
    float* out = (float*)d_out;

    prep_weights<<<K3, 256>>>(Ws2, Wt2, Wi2, Wf, bs2, bt2, bi2, bff);
    proj_points<<<NPTS/8, 256>>>(F, Ws1, Wt1, Wi1, bs1, bt1);
    bilinear_hi<<<NPTS, 384>>>(F, Wi1, bi1);
    dim3 grid(NPTS, H_ / DN);
    gemm_fused<<<grid, 384>>>(dist, mask, Ws1, out);
}